// round 15
// baseline (speedup 1.0000x reference)
#include <cuda_runtime.h>
#include <cuda_bf16.h>
#include <math.h>

// Problem constants
#define N    2048
#define DH   256
#define DK   64
#define FF   32

typedef unsigned long long u64;
typedef unsigned int u32;

// ---------------------------------------------------------------------------
// f32x2 packed helpers (portable PTX, sm_100+)
// ---------------------------------------------------------------------------
__device__ __forceinline__ u64 pack2(float lo, float hi) {
    u64 r;
    asm("mov.b64 %0, {%1, %2};" : "=l"(r) : "f"(lo), "f"(hi));
    return r;
}
__device__ __forceinline__ void unpack2(u64 v, float& lo, float& hi) {
    asm("mov.b64 {%0, %1}, %2;" : "=f"(lo), "=f"(hi) : "l"(v));
}
__device__ __forceinline__ u64 fma2(u64 a, u64 b, u64 c) {
    u64 d;
    asm("fma.rn.f32x2 %0, %1, %2, %3;" : "=l"(d) : "l"(a), "l"(b), "l"(c));
    return d;
}
__device__ __forceinline__ u64 add2(u64 a, u64 b) {
    u64 d;
    asm("add.rn.f32x2 %0, %1, %2;" : "=l"(d) : "l"(a), "l"(b));
    return d;
}
__device__ __forceinline__ u64 dup2(float v) { return pack2(v, v); }
__device__ __forceinline__ u64 relu2(u64 a) {
    float lo, hi;
    unpack2(a, lo, hi);
    lo = fmaxf(lo, 0.0f);
    hi = fmaxf(hi, 0.0f);
    return pack2(lo, hi);
}

// ---------------------------------------------------------------------------
// Scratch (no cudaMalloc allowed)
// ---------------------------------------------------------------------------
#define KSPLIT 16
__device__ float g_q[N * DK];              // Q(x_j): (N, 64)
__device__ float g_k[N * DK];              // K(x_i): (N, 64)
__device__ float g_v[N * DH];              // V(x_j): (N, 256)
__device__ float g_scores[(size_t)N * N];  // k @ q^T
__device__ float g_p[(size_t)N * N];       // logits, then softmax P (in-place)
__device__ float g_part[KSPLIT * (size_t)N * DH];  // split-K partials for P@V

// ---------------------------------------------------------------------------
// Kernel A: q/k/v projections (unchanged from best)
// ---------------------------------------------------------------------------
#define A_ROWS 16
__global__ void __launch_bounds__(256) proj_kernel(
    const float* __restrict__ x,
    const float* __restrict__ Wq, const float* __restrict__ bq,
    const float* __restrict__ Wk, const float* __restrict__ bk,
    const float* __restrict__ Wv, const float* __restrict__ bv)
{
    __shared__ float xs[A_ROWS * DH];
    const int tid = threadIdx.x;
    const int r0  = blockIdx.x * A_ROWS;

    for (int idx = tid; idx < A_ROWS * DH; idx += 256)
        xs[idx] = x[(size_t)r0 * DH + idx];
    __syncthreads();

    for (int g = tid; g < 384; g += 256) {
        const float* W; const float* b; float* out;
        int ld, col;
        if (g < 64)        { W = Wq; b = bq; out = g_q; ld = DK; col = g; }
        else if (g < 128)  { W = Wk; b = bk; out = g_k; ld = DK; col = g - 64; }
        else               { W = Wv; b = bv; out = g_v; ld = DH; col = g - 128; }

        float acc[A_ROWS];
        const float bb = b[col];
#pragma unroll
        for (int r = 0; r < A_ROWS; r++) acc[r] = bb;

#pragma unroll 8
        for (int k = 0; k < DH; k++) {
            const float w = __ldg(&W[k * ld + col]);
#pragma unroll
            for (int r = 0; r < A_ROWS; r++)
                acc[r] = fmaf(xs[r * DH + k], w, acc[r]);
        }
#pragma unroll
        for (int r = 0; r < A_ROWS; r++)
            out[(size_t)(r0 + r) * ld + col] = acc[r];
    }
}

// ---------------------------------------------------------------------------
// Kernel B: scores = k @ q^T (unchanged from best)
// ---------------------------------------------------------------------------
__global__ void __launch_bounds__(256) scores_kernel()
{
    __shared__ float ks[64 * 68];
    __shared__ float qs[64 * 68];
    const int tid = threadIdx.x;
    const int j0 = blockIdx.x * 64;
    const int i0 = blockIdx.y * 64;

    for (int idx = tid; idx < 64 * 64; idx += 256) {
        const int row = idx >> 6;
        const int c   = idx & 63;
        ks[c * 68 + row] = g_k[(size_t)(i0 + row) * DK + c];
        qs[c * 68 + row] = g_q[(size_t)(j0 + row) * DK + c];
    }
    __syncthreads();

    const int ty = tid >> 4, tx = tid & 15;
    u64 acc[4][2];
#pragma unroll
    for (int r = 0; r < 4; r++) { acc[r][0] = 0ULL; acc[r][1] = 0ULL; }

#pragma unroll 8
    for (int c = 0; c < 64; c++) {
        const float4 a4 = *reinterpret_cast<const float4*>(&ks[c * 68 + ty * 4]);
        const ulonglong2 bq2 = *reinterpret_cast<const ulonglong2*>(&qs[c * 68 + tx * 4]);
        u64 ad[4] = { dup2(a4.x), dup2(a4.y), dup2(a4.z), dup2(a4.w) };
        u64 bb[2] = { bq2.x, bq2.y };
#pragma unroll
        for (int r = 0; r < 4; r++)
#pragma unroll
            for (int cc = 0; cc < 2; cc++)
                acc[r][cc] = fma2(ad[r], bb[cc], acc[r][cc]);
    }

#pragma unroll
    for (int r = 0; r < 4; r++) {
        float x0, x1, x2, x3;
        unpack2(acc[r][0], x0, x1);
        unpack2(acc[r][1], x2, x3);
        float4 o = make_float4(x0, x1, x2, x3);
        *reinterpret_cast<float4*>(
            &g_scores[(size_t)(i0 + ty * 4 + r) * N + j0 + tx * 4]) = o;
    }
}

// ---------------------------------------------------------------------------
// Kernel C1: per-pair MLP -> raw logits, register-blocked GEMM formulation.
//
// Block = 256 j's of one row i (grid 16384, 2 CTA/SM).
// Phase 1: thread tid computes h1[0..31] for j = j0+tid -> smem h1s[32][256].
// Phase 2: thread = (jl, og) with jl = tid&15 (owns 8 j-pairs, stride 16),
//          og = tid>>4 (owns o = {2og, 2og+1}). Per ii-chunk of 8: W2 chunk
//          (16 u64) loaded into REGISTERS once, then 128 dependence-free
//          fma2 against 64 conflict-free LDS.64 of h1 pairs. 16 acc chains,
//          same-chain reuse distance 32 cyc >> fma lat 4.
// Phase 3: relu(+b2) dot W3 per o-pair -> smem reduce over 16 og (fixed
//          order, deterministic) -> logit pairs to g_p.
// b3 is softmax-invariant and dropped.
// ---------------------------------------------------------------------------
__global__ void __launch_bounds__(256, 2) mlp_gemm_kernel(
    const float* __restrict__ adj,  const float* __restrict__ dense,
    const float* __restrict__ W1,   const float* __restrict__ b1,
    const float* __restrict__ W2,   const float* __restrict__ b2,
    const float* __restrict__ W3)
{
    __shared__ float h1s[FF][256];       // 32 KB; reused as redbuf in phase 3
    __shared__ __align__(16) u64 w2p[FF * FF];   // 8 KB, [ii][o] dup pairs
    __shared__ float c0s[FF], c1s[FF], c2s[FF], b1s[FF], b2s[FF], w3s[FF];

    const int tid = threadIdx.x;
    const int jl  = tid & 15;            // j-lane: owns pairs jl + 16k
    const int og  = tid >> 4;            // o-group: owns o = 2og, 2og+1
    const int i   = blockIdx.x >> 3;
    const int j0  = (blockIdx.x & 7) * 256;

    if (tid < FF) {
        c0s[tid] = W1[tid];
        c1s[tid] = W1[FF + tid];
        c2s[tid] = W1[2 * FF + tid];
        b1s[tid] = b1[tid];
        b2s[tid] = b2[tid];
        w3s[tid] = W3[tid];
    }
    for (int e = tid; e < FF * FF; e += 256)
        w2p[e] = dup2(W2[e]);            // e = ii*32 + o
    __syncthreads();

    // ---- Phase 1: layer 1 for j = j0 + tid ----
    {
        const float s = g_scores[(size_t)i * N + j0 + tid];
        const float a = adj      [(size_t)i * N + j0 + tid];
        const float d = dense    [(size_t)i * N + j0 + tid];
#pragma unroll
        for (int ii = 0; ii < FF; ii++) {
            float t = fmaf(d, c2s[ii], b1s[ii]);
            t = fmaf(a, c1s[ii], t);
            t = fmaf(s, c0s[ii], t);
            h1s[ii][tid] = fmaxf(t, 0.0f);
        }
    }
    __syncthreads();

    // ---- Phase 2: layer 2 GEMM, W2 chunk in registers ----
    u64 acc0[8], acc1[8];
    {
        const u64 b20 = dup2(b2s[2 * og]);
        const u64 b21 = dup2(b2s[2 * og + 1]);
#pragma unroll
        for (int k = 0; k < 8; k++) { acc0[k] = b20; acc1[k] = b21; }
    }

#pragma unroll
    for (int c = 0; c < 4; c++) {
        u64 w0[8], w1[8];
#pragma unroll
        for (int e = 0; e < 8; e++) {
            const int ii = 8 * c + e;
            w0[e] = w2p[ii * FF + 2 * og];
            w1[e] = w2p[ii * FF + 2 * og + 1];
        }
#pragma unroll
        for (int e = 0; e < 8; e++) {
            const int ii = 8 * c + e;
#pragma unroll
            for (int k = 0; k < 8; k++) {
                const u64 h = *reinterpret_cast<const u64*>(
                    &h1s[ii][2 * (jl + 16 * k)]);
                acc0[k] = fma2(h, w0[e], acc0[k]);
                acc1[k] = fma2(h, w1[e], acc1[k]);
            }
        }
    }

    // ---- Phase 3: epilogue + og reduction ----
    u64 plog[8];
    {
        const u64 w3d0 = dup2(w3s[2 * og]);
        const u64 w3d1 = dup2(w3s[2 * og + 1]);
#pragma unroll
        for (int k = 0; k < 8; k++) {
            u64 t = fma2(relu2(acc0[k]), w3d0, 0ULL);
            plog[k] = fma2(relu2(acc1[k]), w3d1, t);
        }
    }
    __syncthreads();                     // h1s dead; reuse as redbuf

    u64* red = reinterpret_cast<u64*>(h1s);   // [16 og][128 pairs]
#pragma unroll
    for (int k = 0; k < 8; k++)
        red[og * 128 + jl + 16 * k] = plog[k];
    __syncthreads();

    if (tid < 128) {
        u64 s = red[tid];
#pragma unroll
        for (int o = 1; o < 16; o++)
            s = add2(s, red[o * 128 + tid]);
        float l0, l1;
        unpack2(s, l0, l1);
        *reinterpret_cast<float2*>(&g_p[(size_t)i * N + j0 + 2 * tid]) =
            make_float2(l0, l1);
    }
}

// ---------------------------------------------------------------------------
// Kernel C2: in-place row softmax over g_p (unchanged from best)
// ---------------------------------------------------------------------------
__global__ void __launch_bounds__(256) softmax_kernel()
{
    __shared__ float redbuf[8];
    const int tid = threadIdx.x;
    const int i   = blockIdx.x;
    float4* row = reinterpret_cast<float4*>(g_p + (size_t)i * N);

    float4 x0 = row[tid];
    float4 x1 = row[tid + 256];

    float lmax = fmaxf(fmaxf(fmaxf(x0.x, x0.y), fmaxf(x0.z, x0.w)),
                       fmaxf(fmaxf(x1.x, x1.y), fmaxf(x1.z, x1.w)));
#pragma unroll
    for (int off = 16; off > 0; off >>= 1)
        lmax = fmaxf(lmax, __shfl_xor_sync(0xffffffffu, lmax, off));
    if ((tid & 31) == 0) redbuf[tid >> 5] = lmax;
    __syncthreads();
    float m;
    {
        float v = redbuf[tid & 7];
#pragma unroll
        for (int off = 4; off > 0; off >>= 1)
            v = fmaxf(v, __shfl_xor_sync(0xffffffffu, v, off));
        m = v;
    }
    __syncthreads();

    x0.x = __expf(x0.x - m); x0.y = __expf(x0.y - m);
    x0.z = __expf(x0.z - m); x0.w = __expf(x0.w - m);
    x1.x = __expf(x1.x - m); x1.y = __expf(x1.y - m);
    x1.z = __expf(x1.z - m); x1.w = __expf(x1.w - m);

    float lsum = (x0.x + x0.y) + (x0.z + x0.w) + (x1.x + x1.y) + (x1.z + x1.w);
#pragma unroll
    for (int off = 16; off > 0; off >>= 1)
        lsum += __shfl_xor_sync(0xffffffffu, lsum, off);
    if ((tid & 31) == 0) redbuf[tid >> 5] = lsum;
    __syncthreads();
    float stot;
    {
        float v = redbuf[tid & 7];
#pragma unroll
        for (int off = 4; off > 0; off >>= 1)
            v += __shfl_xor_sync(0xffffffffu, v, off);
        stot = v;
    }
    const float rinv = 1.0f / stot;

    x0.x *= rinv; x0.y *= rinv; x0.z *= rinv; x0.w *= rinv;
    x1.x *= rinv; x1.y *= rinv; x1.z *= rinv; x1.w *= rinv;
    row[tid]       = x0;
    row[tid + 256] = x1;
}

// ---------------------------------------------------------------------------
// Kernel D: feature = P @ v via split-K (16 ways) + reduce (unchanged)
// ---------------------------------------------------------------------------
#define AV_BK 16
__global__ void __launch_bounds__(256, 2) av_split_kernel()
{
    __shared__ float ps[AV_BK][132];
    __shared__ float vs[AV_BK][132];

    const int tid = threadIdx.x;
    const int j0    = blockIdx.x * 128;
    const int i0    = blockIdx.y * 128;
    const int kbase = blockIdx.z * (N / KSPLIT);
    const int ty = tid >> 4, tx = tid & 15;

    u64 acc[8][4];
#pragma unroll
    for (int r = 0; r < 8; r++)
#pragma unroll
        for (int c = 0; c < 4; c++) acc[r][c] = 0ULL;

    for (int kt = 0; kt < N / KSPLIT; kt += AV_BK) {
#pragma unroll
        for (int l = 0; l < 8; l++) {
            const int idx = l * 256 + tid;
            const int ii = idx >> 4;
            const int kk = idx & 15;
            ps[kk][ii] = g_p[(size_t)(i0 + ii) * N + kbase + kt + kk];
        }
#pragma unroll
        for (int l = 0; l < 8; l++) {
            const int idx = l * 256 + tid;
            const int kk = idx >> 7;
            const int jj = idx & 127;
            vs[kk][jj] = g_v[(size_t)(kbase + kt + kk) * DH + j0 + jj];
        }
        __syncthreads();

#pragma unroll
        for (int kk = 0; kk < AV_BK; kk++) {
            const float4 a0 = *reinterpret_cast<const float4*>(&ps[kk][ty * 8]);
            const float4 a1 = *reinterpret_cast<const float4*>(&ps[kk][ty * 8 + 4]);
            const ulonglong2 b0 = *reinterpret_cast<const ulonglong2*>(&vs[kk][tx * 8]);
            const ulonglong2 b1 = *reinterpret_cast<const ulonglong2*>(&vs[kk][tx * 8 + 4]);
            u64 ad[8] = { dup2(a0.x), dup2(a0.y), dup2(a0.z), dup2(a0.w),
                          dup2(a1.x), dup2(a1.y), dup2(a1.z), dup2(a1.w) };
            u64 bb[4] = { b0.x, b0.y, b1.x, b1.y };
#pragma unroll
            for (int r = 0; r < 8; r++)
#pragma unroll
                for (int c = 0; c < 4; c++)
                    acc[r][c] = fma2(ad[r], bb[c], acc[r][c]);
        }
        __syncthreads();
    }

    float* dst = g_part + (size_t)blockIdx.z * ((size_t)N * DH);
#pragma unroll
    for (int r = 0; r < 8; r++) {
        const int row = i0 + ty * 8 + r;
        float x0, x1, x2, x3, x4, x5, x6, x7;
        unpack2(acc[r][0], x0, x1);
        unpack2(acc[r][1], x2, x3);
        unpack2(acc[r][2], x4, x5);
        unpack2(acc[r][3], x6, x7);
        float4* d4 = reinterpret_cast<float4*>(&dst[(size_t)row * DH + j0 + tx * 8]);
        d4[0] = make_float4(x0, x1, x2, x3);
        d4[1] = make_float4(x4, x5, x6, x7);
    }
}

// Deterministic fixed-order reduction of the 16 split-K partials.
__global__ void __launch_bounds__(256) av_reduce_kernel(float* __restrict__ out)
{
    const int idx = blockIdx.x * 256 + threadIdx.x;
    const float4* p = reinterpret_cast<const float4*>(g_part);
    float4 s = p[idx];
#pragma unroll
    for (int k = 1; k < KSPLIT; k++) {
        const float4 v = p[(size_t)k * (N * DH / 4) + idx];
        s.x += v.x; s.y += v.y; s.z += v.z; s.w += v.w;
    }
    reinterpret_cast<float4*>(out)[idx] = s;
}

// ---------------------------------------------------------------------------
// Launch. Inputs (metadata order):
//  0 x, 1 adj, 2 dense, 3 Wq, 4 bq, 5 Wk, 6 bk, 7 Wv, 8 bv,
//  9 W1, 10 b1, 11 W2, 12 b2, 13 W3, 14 b3 (softmax-invariant, unused)
// ---------------------------------------------------------------------------
extern "C" void kernel_launch(void* const* d_in, const int* in_sizes, int n_in,
                              void* d_out, int out_size)
{
    const float* x     = (const float*)d_in[0];
    const float* adj   = (const float*)d_in[1];
    const float* dense = (const float*)d_in[2];
    const float* Wq    = (const float*)d_in[3];
    const float* bq    = (const float*)d_in[4];
    const float* Wk    = (const float*)d_in[5];
    const float* bk    = (const float*)d_in[6];
    const float* Wv    = (const float*)d_in[7];
    const float* bv    = (const float*)d_in[8];
    const float* W1    = (const float*)d_in[9];
    const float* b1    = (const float*)d_in[10];
    const float* W2    = (const float*)d_in[11];
    const float* b2    = (const float*)d_in[12];
    const float* W3    = (const float*)d_in[13];
    float* out = (float*)d_out;

    proj_kernel<<<N / A_ROWS, 256>>>(x, Wq, bq, Wk, bk, Wv, bv);
    scores_kernel<<<dim3(N / 64, N / 64), 256>>>();
    mlp_gemm_kernel<<<N * 8, 256>>>(adj, dense, W1, b1, W2, b2, W3);
    softmax_kernel<<<N, 256>>>();
    av_split_kernel<<<dim3(2, 16, KSPLIT), 256>>>();
    av_reduce_kernel<<<N * DH / 4 / 256, 256>>>(out);
}